// round 14
// baseline (speedup 1.0000x reference)
#include <cuda_runtime.h>
#include <cstdint>

#define N_B   32
#define E_DIM 1024
#define IN_DIM 300
#define D_DIM 128
#define NTYPE 3
#define NEG_INF (-9e15f)

// ---------------- persistent device scratch ----------------
__device__ float d_vL[NTYPE][N_B][IN_DIM];
__device__ float d_vR[NTYPE][N_B][IN_DIM];
__device__ float d_Lrow[NTYPE][N_B][E_DIM];
__device__ float d_Rrow[NTYPE][N_B][E_DIM];
__device__ __align__(16) float d_h2[N_B][E_DIM][D_DIM];   // x @ W[2] (16 MB)
__device__ __align__(16) float d_P[N_B][E_DIM][E_DIM];    // softmax probs (134 MB)
__device__ int d_adj_is64;

// ---------------- helpers ----------------
__device__ __forceinline__ uint32_t smem_u32(const void* p) {
    uint32_t a;
    asm("{ .reg .u64 t; cvta.to.shared.u64 t, %1; cvt.u32.u64 %0, t; }" : "=r"(a) : "l"(p));
    return a;
}
#define CP_ASYNC16(dst, src) \
    asm volatile("cp.async.cg.shared.global [%0], [%1], 16;" :: "r"(dst), "l"(src) : "memory")
#define CP_COMMIT() asm volatile("cp.async.commit_group;" ::: "memory")
#define CP_WAIT0()  asm volatile("cp.async.wait_group 0;" ::: "memory")
#define CP_WAIT1()  asm volatile("cp.async.wait_group 1;" ::: "memory")

// ---------------- K0: adj dtype probe ----------------
__global__ __launch_bounds__(256) void k0_detect(const unsigned int* __restrict__ w)
{
    __shared__ unsigned int r[256];
    unsigned int v = 0;
    for (int i = threadIdx.x; i < 4096; i += 256) v |= w[2 * i + 1];
    r[threadIdx.x] = v;
    __syncthreads();
    for (int s = 128; s; s >>= 1) {
        if (threadIdx.x < s) r[threadIdx.x] |= r[threadIdx.x + s];
        __syncthreads();
    }
    if (threadIdx.x == 0) d_adj_is64 = (r[0] == 0u) ? 1 : 0;
}

// ---------------- K1: gates + projected attention vectors ----------------
__global__ __launch_bounds__(256) void k1_gates(
    const float* __restrict__ q, const float* __restrict__ W,
    const float* __restrict__ a, const float* __restrict__ qW1,
    const float* __restrict__ qW2)
{
    int t = blockIdx.x;
    int n = blockIdx.y;
    int tid = threadIdx.x;
    __shared__ float qs[IN_DIM];
    __shared__ float r1[256];
    __shared__ float ga[256];

    for (int k = tid; k < IN_DIM; k += 256) qs[k] = q[n * IN_DIM + k];
    __syncthreads();
    {
        float acc = 0.f;
        const float* w = qW1 + (size_t)t * IN_DIM * 256 + tid;
        #pragma unroll 4
        for (int k = 0; k < IN_DIM; k++) acc += qs[k] * w[(size_t)k * 256];
        r1[tid] = fmaxf(acc, 0.f);
    }
    __syncthreads();
    {
        float acc = 0.f;
        const float* w = qW2 + (size_t)t * 256 * 256 + tid;
        #pragma unroll 4
        for (int k = 0; k < 256; k++) acc += r1[k] * w[(size_t)k * 256];
        float g = 1.f / (1.f + __expf(-acc));
        ga[tid] = g * a[t * 256 + tid];
    }
    __syncthreads();
    for (int k = tid; k < IN_DIM; k += 256) {
        const float* w = W + ((size_t)t * IN_DIM + k) * D_DIM;
        float aL = 0.f, aR = 0.f;
        #pragma unroll 4
        for (int dd = 0; dd < D_DIM; dd++) {
            float wv = w[dd];
            aL += wv * ga[dd];
            aR += wv * ga[128 + dd];
        }
        d_vL[t][n][k] = aL;
        d_vR[t][n][k] = aR;
    }
}

// ---------------- K2a: left/right tables ----------------
__global__ __launch_bounds__(256) void k2a_leftright(const float* __restrict__ x)
{
    int gw = (blockIdx.x * 256 + threadIdx.x) >> 5;
    int lane = threadIdx.x & 31;
    int n = gw >> 10;
    int e = gw & 1023;
    const float* row = x + (size_t)(n * E_DIM + e) * IN_DIM;
    float s0 = 0.f, s1 = 0.f, s2 = 0.f, s3 = 0.f, s4 = 0.f, s5 = 0.f;
    for (int k = lane; k < IN_DIM; k += 32) {
        float xv = row[k];
        s0 += xv * d_vL[0][n][k];  s1 += xv * d_vR[0][n][k];
        s2 += xv * d_vL[1][n][k];  s3 += xv * d_vR[1][n][k];
        s4 += xv * d_vL[2][n][k];  s5 += xv * d_vR[2][n][k];
    }
    #pragma unroll
    for (int o = 16; o; o >>= 1) {
        s0 += __shfl_xor_sync(0xffffffffu, s0, o);
        s1 += __shfl_xor_sync(0xffffffffu, s1, o);
        s2 += __shfl_xor_sync(0xffffffffu, s2, o);
        s3 += __shfl_xor_sync(0xffffffffu, s3, o);
        s4 += __shfl_xor_sync(0xffffffffu, s4, o);
        s5 += __shfl_xor_sync(0xffffffffu, s5, o);
    }
    if (lane == 0) {
        d_Lrow[0][n][e] = s0;  d_Rrow[0][n][e] = s1;
        d_Lrow[1][n][e] = s2;  d_Rrow[1][n][e] = s3;
        d_Lrow[2][n][e] = s4;  d_Rrow[2][n][e] = s5;
    }
}

// ---------------- K3: single-pass softmax -> P (f32) ----------------
__global__ __launch_bounds__(256) void k3_softmax(const void* __restrict__ adjv)
{
    int n = blockIdx.y;
    int i = blockIdx.x * 8 + (threadIdx.x >> 5);
    int lane = threadIdx.x & 31;
    int tid = threadIdx.x;
    int is64 = d_adj_is64;

    __shared__ float Rs[4][E_DIM];   // row 3 = zero pad (safe OOB target)
    for (int idx = tid; idx < 4 * E_DIM; idx += 256) {
        int t = idx >> 10, j = idx & 1023;
        Rs[t][j] = (t < 3) ? d_Rrow[t][n][j] : 0.f;
    }
    __syncthreads();

    float L0 = d_Lrow[0][n][i], L1 = d_Lrow[1][n][i], L2 = d_Lrow[2][n][i];
    size_t rowoff = ((size_t)(n * E_DIM + i)) << 10;
    const int* arow32 = (const int*)adjv + rowoff;
    const long long* arow64 = (const long long*)adjv + rowoff;

    float e[8][4];
    float sum = 0.f;
    #pragma unroll
    for (int m = 0; m < 8; m++) {
        int j0 = m * 128 + lane * 4;
        int av[4];
        if (!is64) {
            int4 v = *reinterpret_cast<const int4*>(&arow32[j0]);
            av[0] = v.x; av[1] = v.y; av[2] = v.z; av[3] = v.w;
        } else {
            av[0] = (int)arow64[j0];     av[1] = (int)arow64[j0 + 1];
            av[2] = (int)arow64[j0 + 2]; av[3] = (int)arow64[j0 + 3];
        }
        #pragma unroll
        for (int b = 0; b < 4; b++) {
            int a = av[b];
            float Lt = (a == 1) ? L0 : ((a == 2) ? L1 : L2);
            float Rt = Rs[(a - 1) & 3][j0 + b];
            float v = Lt + Rt;
            float lv = fmaxf(v, 0.2f * v);
            float ev = (a > 0) ? __expf(lv) : 0.f;
            e[m][b] = ev;
            sum += ev;
        }
    }
    #pragma unroll
    for (int o = 16; o; o >>= 1) sum += __shfl_xor_sync(0xffffffffu, sum, o);
    float rinv = 1.f / sum;
    #pragma unroll
    for (int m = 0; m < 8; m++) {
        int j0 = m * 128 + lane * 4;
        float4 pv = make_float4(e[m][0] * rinv, e[m][1] * rinv,
                                e[m][2] * rinv, e[m][3] * rinv);
        *reinterpret_cast<float4*>(&d_P[n][i][j0]) = pv;
    }
}

// ---------------- K2b: h2 = x @ W[2] (unchanged) ----------------
#define BK2 20
#define K2B_PS 132
#define K2B_HS 136
__global__ __launch_bounds__(256, 2) void k2b_h2(
    const float* __restrict__ x, const float* __restrict__ W)
{
    __shared__ float2 As2[BK2][K2B_PS];
    __shared__ float  Bs[BK2][K2B_HS];

    int n = blockIdx.y;
    int e0 = blockIdx.x * 128;
    const float* W2 = W + (size_t)2 * IN_DIM * D_DIM;
    int tid = threadIdx.x;
    int tx = tid & 15, ty = tid >> 4;
    int le = tid >> 1;
    int lk = (tid & 1) * 10;

    unsigned long long acc[8][4];
    #pragma unroll
    for (int j = 0; j < 8; j++)
        #pragma unroll
        for (int p = 0; p < 4; p++) acc[j][p] = 0ull;

    for (int k0 = 0; k0 < IN_DIM; k0 += BK2) {
        __syncthreads();
        {
            const float* xr = x + ((size_t)(n * E_DIM + e0 + le) * IN_DIM + k0 + lk);
            #pragma unroll
            for (int u = 0; u < 10; u++) {
                float v = xr[u];
                As2[lk + u][le] = make_float2(v, v);
            }
        }
        #pragma unroll
        for (int u = 0; u < 10; u++) {
            int idx = tid + 256 * u;
            int k = idx >> 7, dd = idx & 127;
            Bs[k][dd] = W2[(size_t)(k0 + k) * D_DIM + dd];
        }
        __syncthreads();
        #pragma unroll 5
        for (int k = 0; k < BK2; k++) {
            unsigned long long af[8];
            const ulonglong2* ap =
                reinterpret_cast<const ulonglong2*>(&As2[k][ty * 8]);
            #pragma unroll
            for (int q = 0; q < 4; q++) { ulonglong2 v = ap[q]; af[2*q] = v.x; af[2*q+1] = v.y; }
            unsigned long long bf[4];
            #pragma unroll
            for (int p = 0; p < 4; p++)
                bf[p] = *reinterpret_cast<const unsigned long long*>(&Bs[k][32 * p + 2 * tx]);
            #pragma unroll
            for (int j = 0; j < 8; j++)
                #pragma unroll
                for (int p = 0; p < 4; p++)
                    asm("fma.rn.f32x2 %0, %1, %2, %0;"
                        : "+l"(acc[j][p]) : "l"(af[j]), "l"(bf[p]));
        }
    }
    #pragma unroll
    for (int j = 0; j < 8; j++) {
        float* row = &d_h2[n][e0 + ty * 8 + j][0];
        #pragma unroll
        for (int p = 0; p < 4; p++) {
            unsigned int lo, hi;
            asm("mov.b64 {%0, %1}, %2;" : "=r"(lo), "=r"(hi) : "l"(acc[j][p]));
            *reinterpret_cast<float2*>(row + 32 * p + 2 * tx) =
                make_float2(__uint_as_float(lo), __uint_as_float(hi));
        }
    }
}

// ---------------- K4: double-buffered GEMM out[n] = P^T @ h2[n] ----------------
// 256 threads, 128j x 128d, i-chunks of 32, 2-stage cp.async pipeline.
#define K4_CH 32
#define K4_S  132                          // smem row stride in floats
#define K4_TILEF (K4_CH * K4_S)            // floats per tile (4224)
#define K4_SMEM (4 * K4_TILEF * 4)         // 67584 B: P0,H0,P1,H1
__global__ __launch_bounds__(256, 2) void k4_pv(float* __restrict__ out)
{
    extern __shared__ float sm[];
    int n = blockIdx.y, j0 = blockIdx.x * 128;
    int tid = threadIdx.x;
    int tx = tid & 15, ty = tid >> 4;
    uint32_t smb = smem_u32(sm);

    // per-thread load coords: 4 float4 per tile per thread
    int lrow[4], lc4[4];
    #pragma unroll
    for (int c = 0; c < 4; c++) {
        int f4 = tid + 256 * c;
        lrow[c] = f4 >> 5;
        lc4[c]  = (f4 & 31) * 4;
    }

    unsigned long long acc[8][4];
    #pragma unroll
    for (int j = 0; j < 8; j++)
        #pragma unroll
        for (int p = 0; p < 4; p++) acc[j][p] = 0ull;

    // prologue: issue chunk 0
    {
        int i0 = 0;
        uint32_t pb = smb, hb = smb + K4_TILEF * 4u;
        #pragma unroll
        for (int c = 0; c < 4; c++) {
            uint32_t soff = (uint32_t)(lrow[c] * K4_S + lc4[c]) * 4u;
            CP_ASYNC16(pb + soff, &d_P[n][i0 + lrow[c]][j0 + lc4[c]]);
            CP_ASYNC16(hb + soff, &d_h2[n][i0 + lrow[c]][lc4[c]]);
        }
        CP_COMMIT();
    }

    for (int it = 0; it < 32; it++) {
        int buf = it & 1;
        if (it < 31) {   // issue chunk it+1 into the other buffer
            int i0n = (it + 1) * K4_CH;
            uint32_t base = smb + (uint32_t)((it + 1) & 1) * (2u * K4_TILEF * 4u);
            uint32_t pb = base, hb = base + K4_TILEF * 4u;
            #pragma unroll
            for (int c = 0; c < 4; c++) {
                uint32_t soff = (uint32_t)(lrow[c] * K4_S + lc4[c]) * 4u;
                CP_ASYNC16(pb + soff, &d_P[n][i0n + lrow[c]][j0 + lc4[c]]);
                CP_ASYNC16(hb + soff, &d_h2[n][i0n + lrow[c]][lc4[c]]);
            }
            CP_COMMIT();
            CP_WAIT1();          // chunk it complete, it+1 in flight
        } else {
            CP_WAIT0();
        }
        __syncthreads();         // chunk it visible to all

        const float* Ps = sm + (uint32_t)buf * (2u * K4_TILEF);
        const float* Hs = Ps + K4_TILEF;
        #pragma unroll 4
        for (int k = 0; k < K4_CH; k++) {
            float af[8];
            {
                const float4* a4 = reinterpret_cast<const float4*>(&Ps[k * K4_S + ty * 8]);
                float4 v0 = a4[0], v1 = a4[1];
                af[0] = v0.x; af[1] = v0.y; af[2] = v0.z; af[3] = v0.w;
                af[4] = v1.x; af[5] = v1.y; af[6] = v1.z; af[7] = v1.w;
            }
            unsigned long long ad[8];
            #pragma unroll
            for (int j = 0; j < 8; j++)
                asm("mov.b64 %0, {%1, %1};" : "=l"(ad[j]) : "r"(__float_as_uint(af[j])));
            unsigned long long bf[4];
            #pragma unroll
            for (int p = 0; p < 4; p++)
                bf[p] = *reinterpret_cast<const unsigned long long*>(&Hs[k * K4_S + 32 * p + 2 * tx]);
            #pragma unroll
            for (int j = 0; j < 8; j++)
                #pragma unroll
                for (int p = 0; p < 4; p++)
                    asm("fma.rn.f32x2 %0, %1, %2, %0;"
                        : "+l"(acc[j][p]) : "l"(ad[j]), "l"(bf[p]));
        }
        __syncthreads();         // compute(it) done before buffer reuse
    }
    // epilogue: out[n][j0 + ty*8 + j][32p + 2tx + {0,1}]
    #pragma unroll
    for (int j = 0; j < 8; j++) {
        float* row = out + ((size_t)n * E_DIM + j0 + ty * 8 + j) * D_DIM;
        #pragma unroll
        for (int p = 0; p < 4; p++) {
            unsigned int lo, hi;
            asm("mov.b64 {%0, %1}, %2;" : "=r"(lo), "=r"(hi) : "l"(acc[j][p]));
            *reinterpret_cast<float2*>(row + 32 * p + 2 * tx) =
                make_float2(__uint_as_float(lo), __uint_as_float(hi));
        }
    }
}

// ---------------- launch ----------------
extern "C" void kernel_launch(void* const* d_in, const int* in_sizes, int n_in,
                              void* d_out, int out_size)
{
    const float*  input_state = (const float*)d_in[0];
    const void*   adj         = (const void*)d_in[1];
    const float*  query_vec   = (const float*)d_in[3];
    const float*  W           = (const float*)d_in[4];
    const float*  a           = (const float*)d_in[5];
    const float*  qW1         = (const float*)d_in[6];
    const float*  qW2         = (const float*)d_in[7];
    float* out = (float*)d_out;
    (void)in_sizes; (void)n_in; (void)out_size;

    cudaFuncSetAttribute(k4_pv, cudaFuncAttributeMaxDynamicSharedMemorySize, K4_SMEM);

    k0_detect<<<1, 256>>>((const unsigned int*)adj);
    k1_gates<<<dim3(NTYPE, N_B), 256>>>(query_vec, W, a, qW1, qW2);
    k2a_leftright<<<(N_B * E_DIM) / 8, 256>>>(input_state);
    k3_softmax<<<dim3(128, N_B), 256>>>(adj);
    k2b_h2<<<dim3(8, N_B), 256>>>(input_state, W);
    k4_pv<<<dim3(8, N_B), 256, K4_SMEM>>>(out);
}